// round 17
// baseline (speedup 1.0000x reference)
#include <cuda_runtime.h>
#include <cuda_fp16.h>
#include <math_constants.h>
#include <cstdint>

// Problem constants
#define BATCH 8
#define C_IN  512
#define C_OUT 512
#define C_KEY 256
#define NTOK  2048

// ---------------------------------------------------------------------------
// Scratch (__device__ globals; no cudaMalloc allowed)
// ---------------------------------------------------------------------------
__device__ float g_xt[BATCH * NTOK * C_IN];   // xT[b][n][c]
__device__ float g_qt[BATCH * NTOK * C_KEY];  // qT[b][n][ck]
__device__ float g_kt[BATCH * NTOK * C_KEY];  // kT[b][n][ck]
__device__ float g_v [BATCH * C_OUT * NTOK];  // v[b][c][i]  (i contiguous)
__device__ float g_s [BATCH * NTOK * NTOK];   // ST[b][j][i] -> attnT in place

#define RS 16                                  // softmax row-split
__device__ float g_pm[BATCH * RS * NTOK];      // partial max
__device__ float g_ps[BATCH * RS * NTOK];      // partial sum

// ---------------------------------------------------------------------------
// Base-PTX helpers (valid on .target sm_103 — no tcgen05)
// ---------------------------------------------------------------------------
__device__ __forceinline__ void mma_f16(float* d, const uint32_t* a,
                                        const uint32_t* b)
{
    asm volatile(
        "mma.sync.aligned.m16n8k16.row.col.f32.f16.f16.f32 "
        "{%0,%1,%2,%3}, {%4,%5,%6,%7}, {%8,%9}, {%0,%1,%2,%3};"
        : "+f"(d[0]), "+f"(d[1]), "+f"(d[2]), "+f"(d[3])
        : "r"(a[0]), "r"(a[1]), "r"(a[2]), "r"(a[3]),
          "r"(b[0]), "r"(b[1]));
}

__device__ __forceinline__ uint32_t smem_to_u32(const void* p) {
    uint32_t a;
    asm("{ .reg .u64 t; cvta.to.shared.u64 t, %1; cvt.u32.u64 %0, t; }"
        : "=r"(a) : "l"(p));
    return a;
}
__device__ __forceinline__ void cp16(uint32_t dst, const float* src) {
    asm volatile("cp.async.cg.shared.global [%0], [%1], 16;"
                 :: "r"(dst), "l"(src));
}
#define CP_COMMIT() asm volatile("cp.async.commit_group;" ::: "memory")
#define CP_WAIT2()  asm volatile("cp.async.wait_group 2;" ::: "memory")

__device__ __forceinline__ uint32_t f2h2(float x, float y) {
    __half2 h = __float22half2_rn(make_float2(x, y));
    return *reinterpret_cast<uint32_t*>(&h);
}
__device__ __forceinline__ float2 h2f2(uint32_t u) {
    return __half22float2(*reinterpret_cast<const __half2*>(&u));
}

// ===========================================================================
// Pipelined fp16 tensor-core GEMM:  D[m,n] = sum_k A[m,k]*B[n,k] (K-major f32)
//
// 3-stage cp.async pipeline of RAW fp32 tiles (R14 skeleton, HW-verified
// 2 CTA/SM at this smem size). fp16 conversion at fragment-load time:
//   SPLIT=true : hi = rn_f16(x*S), lo = rn_f16(x*S - hi); 3 mma passes
//                (hh, lo_a*hi_b, hi_a*lo_b); exact 2^-18 descale.
//   SPLIT=false: single pass, unit scale (2^-11 roundoff, = tf32).
// CTA 128x128, BK=32, 256 thr, 8 warps of 64x32. m16n8k16.
// EPI_T: store C[n][m] instead of C[m][n].
// ===========================================================================
#define LDF 36
#define TILE_F (128 * LDF)                    // 4608 floats / 18432 B
#define STAGES 3
#define SMEM_BYTES (STAGES * 2 * TILE_F * 4)  // 110592 B

template <bool SPLIT, bool EPI_T>
__global__ __launch_bounds__(256, 2)
void hp_gemm(const float* __restrict__ A, const float* __restrict__ B,
             float* __restrict__ C,
             int K, int lda, int ldb, int ldc,
             long sA, long sB, long sC)
{
    constexpr float SAs = SPLIT ? 1024.0f : 1.0f;
    constexpr float SBs = SPLIT ? 256.0f  : 1.0f;
    constexpr float DSC = SPLIT ? (1.0f / (1024.0f * 256.0f)) : 1.0f;

    extern __shared__ float smx[];
    const uint32_t sbase = smem_to_u32(smx);

    const int t   = threadIdx.x;
    const int l   = t & 31;
    const int w   = t >> 5;
    const int gid = l >> 2;        // 0..7
    const int tid = l & 3;         // 0..3
    const int wm  = w >> 2;        // 0..1 -> m offset wm*64
    const int wn  = w & 3;         // 0..3 -> n offset wn*32

    A += (long)blockIdx.z * sA;
    B += (long)blockIdx.z * sB;
    C += (long)blockIdx.z * sC;
    const int m0 = blockIdx.y * 128;
    const int n0 = blockIdx.x * 128;

    // loader lanes: 8 lanes cover one row's 32 floats (128B, coalesced)
    const int lr = t >> 3;         // 0..31
    const int lc = (t & 7) * 4;    // 0,4,...,28

    const int nt = K / 32;

    auto load_stage = [&](int stg, int k0) {
        const uint32_t ab = sbase + (uint32_t)stg * (2 * TILE_F * 4);
        const uint32_t bb = ab + TILE_F * 4;
#pragma unroll
        for (int p = 0; p < 4; ++p) {
            const int r = lr + p * 32;
            const uint32_t so = (uint32_t)(r * LDF + lc) * 4;
            cp16(ab + so, A + (long)(m0 + r) * lda + k0 + lc);
            cp16(bb + so, B + (long)(n0 + r) * ldb + k0 + lc);
        }
    };

    float acc[4][4][4];
#pragma unroll
    for (int mi = 0; mi < 4; ++mi)
#pragma unroll
        for (int ni = 0; ni < 4; ++ni)
#pragma unroll
            for (int c = 0; c < 4; ++c) acc[mi][ni][c] = 0.f;

    // prologue: fill the pipeline (nt >= 8 for all shapes here)
    load_stage(0, 0);  CP_COMMIT();
    load_stage(1, 32); CP_COMMIT();
    load_stage(2, 64); CP_COMMIT();

    int stg = 0;
#pragma unroll 1
    for (int tt = 0; tt < nt; ++tt) {
        CP_WAIT2();            // stage `stg` complete
        __syncthreads();

        const float* Ar = smx + stg * 2 * TILE_F;
        const float* Br = Ar + TILE_F;

        // ---- 2 k-steps of 16 ----
#pragma unroll
        for (int s = 0; s < 2; ++s) {
            const int ks = s * 16;

            // B hi fragments
            uint32_t bh[4][2];
#pragma unroll
            for (int ni = 0; ni < 4; ++ni) {
                const float* bp = &Br[(wn * 32 + ni * 8 + gid) * LDF + ks + 2 * tid];
                const float2 b0 = *(const float2*)bp;
                const float2 b1 = *(const float2*)(bp + 8);
                bh[ni][0] = f2h2(b0.x * SBs, b0.y * SBs);
                bh[ni][1] = f2h2(b1.x * SBs, b1.y * SBs);
            }
            // A hi fragments
            uint32_t ah[4][4];
#pragma unroll
            for (int mi = 0; mi < 4; ++mi) {
                const float* ap = &Ar[(wm * 64 + mi * 16 + gid) * LDF + ks + 2 * tid];
                const float2 a0 = *(const float2*)ap;
                const float2 a1 = *(const float2*)(ap + 8 * LDF);
                const float2 a2 = *(const float2*)(ap + 8);
                const float2 a3 = *(const float2*)(ap + 8 * LDF + 8);
                ah[mi][0] = f2h2(a0.x * SAs, a0.y * SAs);
                ah[mi][1] = f2h2(a1.x * SAs, a1.y * SAs);
                ah[mi][2] = f2h2(a2.x * SAs, a2.y * SAs);
                ah[mi][3] = f2h2(a3.x * SAs, a3.y * SAs);
            }
            // pass 1: hi*hi
#pragma unroll
            for (int mi = 0; mi < 4; ++mi)
#pragma unroll
                for (int ni = 0; ni < 4; ++ni)
                    mma_f16(acc[mi][ni], ah[mi], bh[ni]);

            if (SPLIT) {
                // pass 2: lo_a * hi_b  (recompute lo per mi from smem + ah)
#pragma unroll
                for (int mi = 0; mi < 4; ++mi) {
                    const float* ap = &Ar[(wm * 64 + mi * 16 + gid) * LDF + ks + 2 * tid];
                    const float2 a0 = *(const float2*)ap;
                    const float2 a1 = *(const float2*)(ap + 8 * LDF);
                    const float2 a2 = *(const float2*)(ap + 8);
                    const float2 a3 = *(const float2*)(ap + 8 * LDF + 8);
                    const float2 h0 = h2f2(ah[mi][0]);
                    const float2 h1 = h2f2(ah[mi][1]);
                    const float2 h2 = h2f2(ah[mi][2]);
                    const float2 h3 = h2f2(ah[mi][3]);
                    uint32_t al[4];
                    al[0] = f2h2(a0.x * SAs - h0.x, a0.y * SAs - h0.y);
                    al[1] = f2h2(a1.x * SAs - h1.x, a1.y * SAs - h1.y);
                    al[2] = f2h2(a2.x * SAs - h2.x, a2.y * SAs - h2.y);
                    al[3] = f2h2(a3.x * SAs - h3.x, a3.y * SAs - h3.y);
#pragma unroll
                    for (int ni = 0; ni < 4; ++ni)
                        mma_f16(acc[mi][ni], al, bh[ni]);
                }
                // pass 3: hi_a * lo_b
#pragma unroll
                for (int ni = 0; ni < 4; ++ni) {
                    const float* bp = &Br[(wn * 32 + ni * 8 + gid) * LDF + ks + 2 * tid];
                    const float2 b0 = *(const float2*)bp;
                    const float2 b1 = *(const float2*)(bp + 8);
                    const float2 h0 = h2f2(bh[ni][0]);
                    const float2 h1 = h2f2(bh[ni][1]);
                    uint32_t bl[2];
                    bl[0] = f2h2(b0.x * SBs - h0.x, b0.y * SBs - h0.y);
                    bl[1] = f2h2(b1.x * SBs - h1.x, b1.y * SBs - h1.y);
#pragma unroll
                    for (int mi = 0; mi < 4; ++mi)
                        mma_f16(acc[mi][ni], ah[mi], bl);
                }
            }
        }

        __syncthreads();       // all warps done with stage before refill
        if (tt + STAGES < nt) load_stage(stg, (tt + STAGES) * 32);
        CP_COMMIT();           // uniform group accounting
        stg = (stg == STAGES - 1) ? 0 : stg + 1;
    }

    // ---- epilogue (exact descale when SPLIT) ----
#pragma unroll
    for (int mi = 0; mi < 4; ++mi) {
#pragma unroll
        for (int ni = 0; ni < 4; ++ni) {
            const int row = m0 + wm * 64 + mi * 16 + gid;
            const int col = n0 + wn * 32 + ni * 8 + 2 * tid;
            float a4[4];
#pragma unroll
            for (int c = 0; c < 4; ++c) a4[c] = acc[mi][ni][c] * DSC;
            if (!EPI_T) {
                *(float2*)&C[(long)row * ldc + col] = make_float2(a4[0], a4[1]);
                *(float2*)&C[(long)(row + 8) * ldc + col] = make_float2(a4[2], a4[3]);
            } else {
                C[(long)col * ldc + row]           = a4[0];
                C[(long)(col + 1) * ldc + row]     = a4[1];
                C[(long)col * ldc + row + 8]       = a4[2];
                C[(long)(col + 1) * ldc + row + 8] = a4[3];
            }
        }
    }
}

// ---------------------------------------------------------------------------
// Transpose x[b][c][n] -> xT[b][n][c]
// ---------------------------------------------------------------------------
__global__ __launch_bounds__(256)
void transpose_x(const float* __restrict__ x, float* __restrict__ xt)
{
    __shared__ float tile[32][33];
    const float* xb = x + (long)blockIdx.z * C_IN * NTOK;
    float* xtb = xt + (long)blockIdx.z * NTOK * C_IN;
    const int n0 = blockIdx.x * 32, c0 = blockIdx.y * 32;
    const int tx = threadIdx.x & 31, ty = threadIdx.x >> 5;
#pragma unroll
    for (int i = ty; i < 32; i += 8)
        tile[i][tx] = xb[(long)(c0 + i) * NTOK + n0 + tx];
    __syncthreads();
#pragma unroll
    for (int i = ty; i < 32; i += 8)
        xtb[(long)(n0 + i) * C_IN + c0 + tx] = tile[tx][i];
}

// ---------------------------------------------------------------------------
// Parallel column softmax over ST[b][j][i] along j, in place.
// ---------------------------------------------------------------------------
#define RCHUNK (NTOK / RS)   // 128

__global__ __launch_bounds__(256)
void softmax_part(const float* __restrict__ S,
                  float* __restrict__ pm, float* __restrict__ ps)
{
    const int b  = blockIdx.z, rs = blockIdx.y;
    const int c0 = (blockIdx.x * 256 + threadIdx.x) * 4;
    const float* p = S + (long)b * NTOK * NTOK + (long)rs * RCHUNK * NTOK + c0;

    float4 m = make_float4(-CUDART_INF_F, -CUDART_INF_F,
                           -CUDART_INF_F, -CUDART_INF_F);
    float4 s = make_float4(0.f, 0.f, 0.f, 0.f);
#pragma unroll 4
    for (int j = 0; j < RCHUNK; ++j) {
        const float4 v = *(const float4*)&p[(long)j * NTOK];
        float4 mn;
        mn.x = fmaxf(m.x, v.x); mn.y = fmaxf(m.y, v.y);
        mn.z = fmaxf(m.z, v.z); mn.w = fmaxf(m.w, v.w);
        s.x = s.x * __expf(m.x - mn.x) + __expf(v.x - mn.x);
        s.y = s.y * __expf(m.y - mn.y) + __expf(v.y - mn.y);
        s.z = s.z * __expf(m.z - mn.z) + __expf(v.z - mn.z);
        s.w = s.w * __expf(m.w - mn.w) + __expf(v.w - mn.w);
        m = mn;
    }
    const long po = (long)(b * RS + rs) * NTOK + c0;
    *(float4*)&pm[po] = m;
    *(float4*)&ps[po] = s;
}

__global__ __launch_bounds__(256)
void softmax_norm(float* __restrict__ S,
                  const float* __restrict__ pm, const float* __restrict__ ps)
{
    const int b  = blockIdx.z, rs = blockIdx.y;
    const int c0 = (blockIdx.x * 256 + threadIdx.x) * 4;

    float4 m = make_float4(-CUDART_INF_F, -CUDART_INF_F,
                           -CUDART_INF_F, -CUDART_INF_F);
    float4 s = make_float4(0.f, 0.f, 0.f, 0.f);
#pragma unroll
    for (int r = 0; r < RS; ++r) {
        const long po = (long)(b * RS + r) * NTOK + c0;
        const float4 pmr = *(const float4*)&pm[po];
        const float4 psr = *(const float4*)&ps[po];
        float4 mn;
        mn.x = fmaxf(m.x, pmr.x); mn.y = fmaxf(m.y, pmr.y);
        mn.z = fmaxf(m.z, pmr.z); mn.w = fmaxf(m.w, pmr.w);
        s.x = s.x * __expf(m.x - mn.x) + psr.x * __expf(pmr.x - mn.x);
        s.y = s.y * __expf(m.y - mn.y) + psr.y * __expf(pmr.y - mn.y);
        s.z = s.z * __expf(m.z - mn.z) + psr.z * __expf(pmr.z - mn.z);
        s.w = s.w * __expf(m.w - mn.w) + psr.w * __expf(pmr.w - mn.w);
        m = mn;
    }
    const float4 inv = make_float4(1.f / s.x, 1.f / s.y, 1.f / s.z, 1.f / s.w);

    float* p = S + (long)b * NTOK * NTOK + (long)rs * RCHUNK * NTOK + c0;
#pragma unroll 4
    for (int j = 0; j < RCHUNK; ++j) {
        float4 v = *(const float4*)&p[(long)j * NTOK];
        v.x = __expf(v.x - m.x) * inv.x;
        v.y = __expf(v.y - m.y) * inv.y;
        v.z = __expf(v.z - m.z) * inv.z;
        v.w = __expf(v.w - m.w) * inv.w;
        *(float4*)&p[(long)j * NTOK] = v;
    }
}

// ---------------------------------------------------------------------------
// Launch
// ---------------------------------------------------------------------------
extern "C" void kernel_launch(void* const* d_in, const int* in_sizes, int n_in,
                              void* d_out, int out_size)
{
    const float* x  = nullptr;
    const float* Wq = nullptr;
    const float* Wk = nullptr;
    const float* Wv = nullptr;
    for (int i = 0; i < n_in; ++i) {
        const float* p = (const float*)d_in[i];
        if (in_sizes[i] == BATCH * C_IN * NTOK)      x = p;
        else if (in_sizes[i] == C_OUT * C_IN)        Wv = p;
        else if (in_sizes[i] == C_KEY * C_IN) {
            if (!Wq) Wq = p; else Wk = p;
        }
    }

    float *xt, *qt, *kt, *v, *s, *pm, *ps;
    cudaGetSymbolAddress((void**)&xt, g_xt);
    cudaGetSymbolAddress((void**)&qt, g_qt);
    cudaGetSymbolAddress((void**)&kt, g_kt);
    cudaGetSymbolAddress((void**)&v,  g_v);
    cudaGetSymbolAddress((void**)&s,  g_s);
    cudaGetSymbolAddress((void**)&pm, g_pm);
    cudaGetSymbolAddress((void**)&ps, g_ps);
    float* out = (float*)d_out;

    cudaFuncSetAttribute(hp_gemm<true,  true >, cudaFuncAttributeMaxDynamicSharedMemorySize, SMEM_BYTES);
    cudaFuncSetAttribute(hp_gemm<true,  false>, cudaFuncAttributeMaxDynamicSharedMemorySize, SMEM_BYTES);
    cudaFuncSetAttribute(hp_gemm<false, true >, cudaFuncAttributeMaxDynamicSharedMemorySize, SMEM_BYTES);
    cudaFuncSetAttribute(hp_gemm<false, false>, cudaFuncAttributeMaxDynamicSharedMemorySize, SMEM_BYTES);

    // 0) xT[b][n][c] = x[b][c][n]
    transpose_x<<<dim3(NTOK / 32, C_IN / 32, BATCH), 256>>>(x, xt);

    // 1) q/k projections: fp16-split, epilogue-T -> qT/kT[n][o]
    hp_gemm<true, true><<<dim3(NTOK / 128, C_KEY / 128, BATCH), 256, SMEM_BYTES>>>(
        Wq, xt, qt, C_IN, C_IN, C_IN, C_KEY,
        0L, (long)NTOK * C_IN, (long)NTOK * C_KEY);
    hp_gemm<true, true><<<dim3(NTOK / 128, C_KEY / 128, BATCH), 256, SMEM_BYTES>>>(
        Wk, xt, kt, C_IN, C_IN, C_IN, C_KEY,
        0L, (long)NTOK * C_IN, (long)NTOK * C_KEY);

    // 2) v projection: fp16 single pass, epilogue-N -> v[c][i]
    hp_gemm<false, false><<<dim3(NTOK / 128, C_OUT / 128, BATCH), 256, SMEM_BYTES>>>(
        Wv, xt, v, C_IN, C_IN, C_IN, NTOK,
        0L, (long)NTOK * C_IN, (long)C_OUT * NTOK);

    // 3) sim, transposed: ST[j][i] = sum_c qT[j,c] * kT[i,c]  (fp16-split)
    hp_gemm<true, false><<<dim3(NTOK / 128, NTOK / 128, BATCH), 256, SMEM_BYTES>>>(
        qt, kt, s, C_KEY, C_KEY, C_KEY, NTOK,
        (long)NTOK * C_KEY, (long)NTOK * C_KEY, (long)NTOK * NTOK);

    // 4) parallel column softmax (in place): ST -> attnT
    softmax_part<<<dim3(NTOK / 1024, RS, BATCH), 256>>>(s, pm, ps);
    softmax_norm<<<dim3(NTOK / 1024, RS, BATCH), 256>>>(s, pm, ps);

    // 5) out: D[c,m] = sum_i v[c,i] * attnT[m,i]; fp16 single pass,
    //    epilogue-T -> out[m][c]
    hp_gemm<false, true><<<dim3(NTOK / 128, C_OUT / 128, BATCH), 256, SMEM_BYTES>>>(
        v, s, out, NTOK, NTOK, NTOK, C_OUT,
        (long)C_OUT * NTOK, (long)NTOK * NTOK, (long)NTOK * C_OUT);
}